// round 15
// baseline (speedup 1.0000x reference)
#include <cuda_runtime.h>

// K split by t3: g_Ks[t3*27 + (t0*9 + t1*3 + t2)]
__device__ __align__(16) float g_Ks[3 * 27];
__device__ int g_kflag;   // 0 at module load; set (to 1) when g_Ks is published.
                          // K is recomputed identically on EVERY call; the flag
                          // is synchronization only, never skips strip work.

// ---------------------------------------------------------------------------
// Single fused launch. Block 0: parallel shuffle-simulate the 16x16 circuit
// unitary U, M = Re(U^dag Z0 U), sparse 16-term projection to 81 multilinear
// coefficients K; publish + release flag. Non-zero blocks: acquire the flag
// FIRST (before any loads -> fence is cheap on timed replays where the flag
// is already set), copy K to shared, then run the strip body (R3-measured).
//   ev = sum_{t in {1,C,S}^4} K[t] * prod_q e_q(t_q)
// ---------------------------------------------------------------------------
__global__ void __launch_bounds__(256)
qcl_kernel(const float* __restrict__ x, const float* __restrict__ w,
           float* __restrict__ out) {
    __shared__ __align__(16) float sK[3 * 28];   // each 27-part padded to 28
    const int tid = threadIdx.x;

    if (blockIdx.x == 0) {
        // ================= prologue: compute K =================
        __shared__ float sUr[16][17];
        __shared__ float sUi[16][17];
        __shared__ float sM[16][17];
        __shared__ float sgc[24], sgs[24];

        if (tid < 24) {
            float c, s;
            __sincosf(w[tid] * 0.5f, &s, &c);   // |w|<~0.5: fast path accurate
            sgc[tid] = c; sgs[tid] = s;
        }
        __syncthreads();

        // shuffle simulator: thread owns amplitude kk of column col
        {
            const int lane = tid & 31;
            const int kk   = lane & 15;
            const int col  = ((tid >> 5) << 1) | (lane >> 4);

            float ar = (kk == col) ? 1.f : 0.f;
            float ai = 0.f;

            auto rot = [&](int m, float g00r, float g00i, float g01r, float g01i,
                                  float g10r, float g10i, float g11r, float g11i) {
                float pr = __shfl_xor_sync(0xffffffffu, ar, m);
                float pi = __shfl_xor_sync(0xffffffffu, ai, m);
                bool  b  = (kk & m) != 0;
                float ur = b ? pr : ar, ui = b ? pi : ai;
                float wr = b ? ar : pr, wi = b ? ai : pi;
                float c0r = b ? g10r : g00r, c0i = b ? g10i : g00i;
                float c1r = b ? g11r : g01r, c1i = b ? g11i : g01i;
                ar = c0r * ur - c0i * ui + c1r * wr - c1i * wi;
                ai = c0r * ui + c0i * ur + c1r * wi + c1i * wr;
            };
            auto cnot = [&](int mc, int mt) {
                float pr = __shfl_xor_sync(0xffffffffu, ar, mt);
                float pi = __shfl_xor_sync(0xffffffffu, ai, mt);
                if (kk & mc) { ar = pr; ai = pi; }
            };

            #pragma unroll
            for (int g8 = 0; g8 < 8; g8++) {     // layer*4 + q
                int q = g8 & 3;
                int m = 8 >> q;
                int base = g8 * 3;
                float c, s;
                c = sgc[base + 0]; s = sgs[base + 0];      // RX: [[c,-is],[-is,c]]
                rot(m, c, 0.f, 0.f, -s, 0.f, -s, c, 0.f);
                c = sgc[base + 1]; s = sgs[base + 1];      // RY: [[c,-s],[s,c]]
                rot(m, c, 0.f, -s, 0.f, s, 0.f, c, 0.f);
                c = sgc[base + 2]; s = sgs[base + 2];      // RZ: diag(e^-it/2,e^it/2)
                rot(m, c, -s, 0.f, 0.f, 0.f, 0.f, c, s);
                if (q == 3) { cnot(8, 4); cnot(2, 1); cnot(8, 2); cnot(4, 1); }
            }

            sUr[kk][col] = ar;
            sUi[kk][col] = ai;
        }
        __syncthreads();

        // M[i][j] = Re(sum_k z_k conj(U[k][i]) U[k][j]), z_k = (k&8)?-1:+1
        {
            int i = tid >> 4, j = tid & 15;
            float acc = 0.f;
            #pragma unroll
            for (int k = 0; k < 16; k++) {
                float z = (k & 8) ? -1.f : 1.f;
                acc += z * (sUr[k][i] * sUr[k][j] + sUi[k][i] * sUi[k][j]);
            }
            sM[i][j] = acc;
        }
        __syncthreads();

        // sparse projection: K[t] = (1/16) sum_c (-1)^popc(c&smask) * M[c][c^xmask]
        if (tid < 81) {
            int t3 = tid % 3, r = tid / 3;
            int t2 = r % 3;  r /= 3;
            int t1 = r % 3;
            int t0 = r / 3;
            int xmask = ((t0 == 2) << 3) | ((t1 == 2) << 2) | ((t2 == 2) << 1) | (t3 == 2);
            int smask = ((t0 == 1) << 3) | ((t1 == 1) << 2) | ((t2 == 1) << 1) | (t3 == 1);
            float acc = 0.f;
            #pragma unroll
            for (int c = 0; c < 16; c++) {
                float sgn = (__popc(c & smask) & 1) ? -1.f : 1.f;
                acc += sgn * sM[c][c ^ xmask];
            }
            acc *= 0.0625f;
            int e = t0 * 9 + t1 * 3 + t2;
            sK[t3 * 28 + e]   = acc;     // local copy for block 0's own strips
            g_Ks[t3 * 27 + e] = acc;     // publish
        } else if (tid < 84) {
            sK[(tid - 81) * 28 + 27] = 0.f;
        }
        __syncthreads();

        if (tid == 0) {
            __threadfence();             // release g_Ks
            atomicExch(&g_kflag, 1);
        }
    } else {
        // ================= acquire K (BEFORE any loads) =================
        // On timed replays the flag is already 1: one L2 atomic + a fence with
        // no outstanding memory ops (cheap), two barriers — ~R3 startup cost.
        if (tid == 0) {
            while (atomicAdd(&g_kflag, 0) == 0) { __nanosleep(64); }
            __threadfence();             // acquire
        }
        __syncthreads();                 // chain acquire to whole block
        if (tid < 84) {
            int part = tid / 28, idx = tid - part * 28;
            sK[tid] = (idx < 27) ? g_Ks[part * 27 + idx] : 0.f;
        }
        __syncthreads();
    }

    // ================= strip phase (all blocks) — R3 body =================
    // grid sized so every thread owns exactly one strip:
    // strips: 32 per row (last covers 3 pixels), 127 rows, 96 planes
    int sid  = blockIdx.x * blockDim.x + tid;
    int p    = sid / 4064;            // 127*32
    int rem  = sid - p * 4064;
    int h    = rem >> 5;
    int w0   = (rem & 31) << 2;       // 0..124, 16B-aligned
    bool full = (w0 < 124);
    int npix  = full ? 4 : 3;

    const float* r0 = x + p * 16384 + h * 128 + w0;
    float4 t4 = *(const float4*)r0;
    float4 b4 = *(const float4*)(r0 + 128);
    float  t5 = full ? __ldg(r0 + 4)   : 0.f;
    float  b5 = full ? __ldg(r0 + 132) : 0.f;

    float Ct[5], St[5], Cb[5], Sb[5];
    __sincosf(t4.x, &St[0], &Ct[0]);  __sincosf(b4.x, &Sb[0], &Cb[0]);
    __sincosf(t4.y, &St[1], &Ct[1]);  __sincosf(b4.y, &Sb[1], &Cb[1]);
    __sincosf(t4.z, &St[2], &Ct[2]);  __sincosf(b4.z, &Sb[2], &Cb[2]);
    __sincosf(t4.w, &St[3], &Ct[3]);  __sincosf(b4.w, &Sb[3], &Cb[3]);
    __sincosf(t5,   &St[4], &Ct[4]);  __sincosf(b5,   &Sb[4], &Cb[4]);

    const float4* sK4 = (const float4*)sK;       // sK4[part*7 + v], part = t3

    float* o = out + p * 16129 + h * 127 + w0;

    #pragma unroll
    for (int k = 0; k < 4; k++) {
        // wires: 0=top-left, 1=top-right, 2=bottom-left, 3=bottom-right
        float C0 = Ct[k],     S0 = St[k];
        float C1 = Ct[k + 1], S1 = St[k + 1];
        float C2 = Cb[k],     S2 = Sb[k];
        float C3 = Cb[k + 1], S3 = Sb[k + 1];

        // level t3: r[a] = K0[a] + K1[a]*C3 + K2[a]*S3, a = t0*9+t1*3+t2
        float r[28];
        #pragma unroll
        for (int v = 0; v < 7; v++) {
            float4 k0 = sK4[v], k1 = sK4[7 + v], k2 = sK4[14 + v];
            r[4 * v + 0] = fmaf(k1.x, C3, fmaf(k2.x, S3, k0.x));
            r[4 * v + 1] = fmaf(k1.y, C3, fmaf(k2.y, S3, k0.y));
            r[4 * v + 2] = fmaf(k1.z, C3, fmaf(k2.z, S3, k0.z));
            r[4 * v + 3] = fmaf(k1.w, C3, fmaf(k2.w, S3, k0.w));
        }

        // level t2
        float r2[9];
        #pragma unroll
        for (int a = 0; a < 9; a++)
            r2[a] = fmaf(r[3 * a + 1], C2, fmaf(r[3 * a + 2], S2, r[3 * a]));

        // levels t1, t0
        float ra = fmaf(r2[1], C1, fmaf(r2[2], S1, r2[0]));
        float rb = fmaf(r2[4], C1, fmaf(r2[5], S1, r2[3]));
        float rc = fmaf(r2[7], C1, fmaf(r2[8], S1, r2[6]));
        float ev = fmaf(rb, C0, fmaf(rc, S0, ra));

        if (k < npix) o[k] = ev;
    }
}

extern "C" void kernel_launch(void* const* d_in, const int* in_sizes, int n_in,
                              void* d_out, int out_size) {
    const float* x = (const float*)d_in[0];   // [32,3,128,128]
    const float* w = (const float*)d_in[1];   // [2,4,3]
    float* out = (float*)d_out;               // [32,3,127,127]

    // 96 planes * 127 rows * 32 strips = 390144 = 1524 * 256 exactly
    qcl_kernel<<<1524, 256>>>(x, w, out);
}

// round 16
// speedup vs baseline: 1.1174x; 1.1174x over previous
#include <cuda_runtime.h>

// K split by t3: g_Ks[t3*27 + (t0*9 + t1*3 + t2)]
__device__ __align__(16) float g_Ks[3 * 27];

// ---------------------------------------------------------------------------
// Setup kernel: ONE block, 256 threads, NO serial gate chain.
//  1. 24 parallel __sincosf for the weight half-angles.
//  2. 8 threads: per-(layer,qubit) 2x2 complex gate product G = Rz*Ry*Rx.
//  3. 256 threads: each layer unitary entry L[i][j] = prod_q G_q[kk_q][j_q],
//     where kk = CNOT-permutation(i) (entangler folded in as index remap).
//  4. 256 threads: U = L2 @ L1 (16 complex MACs each).
//  5. M = Re(U^dag Z0 U) + sparse 16-term projection to 81 K coefficients.
// ---------------------------------------------------------------------------
__global__ void __launch_bounds__(256)
qcl_setup_kernel(const float* __restrict__ w) {
    __shared__ float sgc[24], sgs[24];
    __shared__ float sG[2][4][8];       // {00r,00i,01r,01i,10r,10i,11r,11i}
    __shared__ float L1r[16][17], L1i[16][17];
    __shared__ float L2r[16][17], L2i[16][17];
    __shared__ float Ur[16][17],  Ui[16][17];
    __shared__ float sM[16][17];

    const int tid = threadIdx.x;

    if (tid < 24) {
        float c, s;
        __sincosf(w[tid] * 0.5f, &s, &c);   // |w|~0.1: fast path plenty accurate
        sgc[tid] = c; sgs[tid] = s;
    }
    __syncthreads();

    // per-(layer,qubit) gate product G = Rz @ Ry @ Rx
    if (tid < 8) {
        int layer = tid >> 2, q = tid & 3;
        int base = (layer * 4 + q) * 3;
        float cx = sgc[base + 0], sx = sgs[base + 0];
        float cy = sgc[base + 1], sy = sgs[base + 1];
        float cz = sgc[base + 2], sz = sgs[base + 2];
        // A = Ry @ Rx
        float A00r = cy * cx,  A00i =  sy * sx;
        float A01r = -sy * cx, A01i = -cy * sx;
        float A10r =  sy * cx, A10i = -cy * sx;
        float A11r =  cy * cx, A11i = -sy * sx;
        // G = Rz @ A : row0 *= (cz - i sz), row1 *= (cz + i sz)
        float* g = sG[layer][q];
        g[0] = cz * A00r + sz * A00i;  g[1] = cz * A00i - sz * A00r;
        g[2] = cz * A01r + sz * A01i;  g[3] = cz * A01i - sz * A01r;
        g[4] = cz * A10r - sz * A10i;  g[5] = cz * A10i + sz * A10r;
        g[6] = cz * A11r - sz * A11i;  g[7] = cz * A11i + sz * A11r;
    }
    __syncthreads();

    // layer unitaries: L[i][j] = (x)G [kk][j], kk = composed CNOT perm of i.
    // state = CN(4,1)·CN(8,2)·CN(2,1)·CN(8,4)·(x)G · v  (masks: wire q -> 8>>q)
    // => kk: apply involutions in REVERSE order starting from row index i.
    {
        int i = tid >> 4, j = tid & 15;
        int kk = i;
        kk ^= (kk & 4) ? 1 : 0;   // CN(4,1)  (last applied -> first inverted)
        kk ^= (kk & 8) ? 2 : 0;   // CN(8,2)
        kk ^= (kk & 2) ? 1 : 0;   // CN(2,1)
        kk ^= (kk & 8) ? 4 : 0;   // CN(8,4)
        #pragma unroll
        for (int layer = 0; layer < 2; layer++) {
            float pr = 1.f, pi = 0.f;
            #pragma unroll
            for (int q = 0; q < 4; q++) {
                int a = (kk >> (3 - q)) & 1;
                int b = (j  >> (3 - q)) & 1;
                const float* g = sG[layer][q] + (a * 2 + b) * 2;
                float gr = g[0], gi = g[1];
                float nr = pr * gr - pi * gi;
                float ni = pr * gi + pi * gr;
                pr = nr; pi = ni;
            }
            if (layer == 0) { L1r[i][j] = pr; L1i[i][j] = pi; }
            else            { L2r[i][j] = pr; L2i[i][j] = pi; }
        }
    }
    __syncthreads();

    // U = L2 @ L1
    {
        int i = tid >> 4, j = tid & 15;
        float ur = 0.f, ui = 0.f;
        #pragma unroll
        for (int k = 0; k < 16; k++) {
            float ar = L2r[i][k], ai = L2i[i][k];
            float br = L1r[k][j], bi = L1i[k][j];
            ur += ar * br - ai * bi;
            ui += ar * bi + ai * br;
        }
        Ur[i][j] = ur; Ui[i][j] = ui;
    }
    __syncthreads();

    // M[i][j] = Re(sum_k z_k conj(U[k][i]) U[k][j]), z_k = (k&8)?-1:+1
    {
        int i = tid >> 4, j = tid & 15;
        float acc = 0.f;
        #pragma unroll
        for (int k = 0; k < 16; k++) {
            float z = (k & 8) ? -1.f : 1.f;
            acc += z * (Ur[k][i] * Ur[k][j] + Ui[k][i] * Ui[k][j]);
        }
        sM[i][j] = acc;
    }
    __syncthreads();

    // sparse projection: K[t] = (1/16) sum_c (-1)^popc(c & smask) * M[c][c^xmask]
    if (tid < 81) {
        int t3 = tid % 3, r = tid / 3;
        int t2 = r % 3;  r /= 3;
        int t1 = r % 3;
        int t0 = r / 3;
        int xmask = ((t0 == 2) << 3) | ((t1 == 2) << 2) | ((t2 == 2) << 1) | (t3 == 2);
        int smask = ((t0 == 1) << 3) | ((t1 == 1) << 2) | ((t2 == 1) << 1) | (t3 == 1);
        float acc = 0.f;
        #pragma unroll
        for (int c = 0; c < 16; c++) {
            float sgn = (__popc(c & smask) & 1) ? -1.f : 1.f;
            acc += sgn * sM[c][c ^ xmask];
        }
        g_Ks[t3 * 27 + (t0 * 9 + t1 * 3 + t2)] = acc * 0.0625f;
    }
}

// ---------------------------------------------------------------------------
// Main kernel: R3/R11 body VERBATIM (measured 12.8 us twice). One thread per
// 4-pixel strip; 5 top + 5 bottom sincos shared; contraction via float4
// shared loads of K.
// ---------------------------------------------------------------------------
__global__ void __launch_bounds__(256)
qcl_main_kernel(const float* __restrict__ x, float* __restrict__ out, int nStrips) {
    __shared__ __align__(16) float sK[3 * 28];   // each 27-part padded to 28
    if (threadIdx.x < 84) {
        int part = threadIdx.x / 28, idx = threadIdx.x - part * 28;
        sK[threadIdx.x] = (idx < 27) ? g_Ks[part * 27 + idx] : 0.f;
    }
    __syncthreads();
    const float4* sK4 = (const float4*)sK;       // sK4[part*7 + v]

    int sid = blockIdx.x * blockDim.x + threadIdx.x;
    if (sid >= nStrips) return;

    // strips: 32 per row (last covers 3 pixels), 127 rows, 96 planes
    int p    = sid / 4064;            // 127*32
    int rem  = sid - p * 4064;
    int h    = rem >> 5;
    int w0   = (rem & 31) << 2;       // 0..124, 16B-aligned
    bool full = (w0 < 124);
    int npix  = full ? 4 : 3;

    const float* r0 = x + p * 16384 + h * 128 + w0;
    float4 t4 = *(const float4*)r0;
    float4 b4 = *(const float4*)(r0 + 128);
    float  t5 = full ? __ldg(r0 + 4)   : 0.f;
    float  b5 = full ? __ldg(r0 + 132) : 0.f;

    float Ct[5], St[5], Cb[5], Sb[5];
    __sincosf(t4.x, &St[0], &Ct[0]);  __sincosf(b4.x, &Sb[0], &Cb[0]);
    __sincosf(t4.y, &St[1], &Ct[1]);  __sincosf(b4.y, &Sb[1], &Cb[1]);
    __sincosf(t4.z, &St[2], &Ct[2]);  __sincosf(b4.z, &Sb[2], &Cb[2]);
    __sincosf(t4.w, &St[3], &Ct[3]);  __sincosf(b4.w, &Sb[3], &Cb[3]);
    __sincosf(t5,   &St[4], &Ct[4]);  __sincosf(b5,   &Sb[4], &Cb[4]);

    float* o = out + p * 16129 + h * 127 + w0;

    #pragma unroll
    for (int k = 0; k < 4; k++) {
        // wires: 0=top-left, 1=top-right, 2=bottom-left, 3=bottom-right
        float C0 = Ct[k],     S0 = St[k];
        float C1 = Ct[k + 1], S1 = St[k + 1];
        float C2 = Cb[k],     S2 = Sb[k];
        float C3 = Cb[k + 1], S3 = Sb[k + 1];

        // level t3: r[a] = K0[a] + K1[a]*C3 + K2[a]*S3, a = t0*9+t1*3+t2
        float r[28];
        #pragma unroll
        for (int v = 0; v < 7; v++) {
            float4 k0 = sK4[v], k1 = sK4[7 + v], k2 = sK4[14 + v];
            r[4 * v + 0] = fmaf(k1.x, C3, fmaf(k2.x, S3, k0.x));
            r[4 * v + 1] = fmaf(k1.y, C3, fmaf(k2.y, S3, k0.y));
            r[4 * v + 2] = fmaf(k1.z, C3, fmaf(k2.z, S3, k0.z));
            r[4 * v + 3] = fmaf(k1.w, C3, fmaf(k2.w, S3, k0.w));
        }

        // level t2
        float r2[9];
        #pragma unroll
        for (int a = 0; a < 9; a++)
            r2[a] = fmaf(r[3 * a + 1], C2, fmaf(r[3 * a + 2], S2, r[3 * a]));

        // levels t1, t0
        float ra = fmaf(r2[1], C1, fmaf(r2[2], S1, r2[0]));
        float rb = fmaf(r2[4], C1, fmaf(r2[5], S1, r2[3]));
        float rc = fmaf(r2[7], C1, fmaf(r2[8], S1, r2[6]));
        float ev = fmaf(rb, C0, fmaf(rc, S0, ra));

        if (k < npix) o[k] = ev;
    }
}

extern "C" void kernel_launch(void* const* d_in, const int* in_sizes, int n_in,
                              void* d_out, int out_size) {
    const float* x = (const float*)d_in[0];   // [32,3,128,128]
    const float* w = (const float*)d_in[1];   // [2,4,3]
    float* out = (float*)d_out;               // [32,3,127,127]

    qcl_setup_kernel<<<1, 256>>>(w);

    const int nStrips = 96 * 127 * 32;         // 390144
    const int blocks  = (nStrips + 255) / 256; // 1524
    qcl_main_kernel<<<blocks, 256>>>(x, out, nStrips);
}